// round 12
// baseline (speedup 1.0000x reference)
#include <cuda_runtime.h>
#include <cstdint>

// Problem shape (fixed for this instance)
#define NUM_SP 2048
#define CCH    64
#define NPIX   (1024 * 1024)

// Accum half-kernel: 128 px x 32 ch per block
#define A_PX   128

// Gather tiling: 16384 px per (cg, chunk) tile, 64 chunks
#define QITER  16
#define PIX_PER_TILE (QITER * 256 * 4)     // 16384
#define N_CHUNKS (NPIX / PIX_PER_TILE)     // 64

// Persistent G0: 296 = 8 cg x 37; chunk stride 37 over 64 chunks
#define G0_BLOCKS 296
#define G0_STRIDE 37

// Scratch (allocation-free rule: __device__ globals)
__device__ float g_sums[NUM_SP * CCH];   // [S, C] row-major, 512 KB (L2-hot)
__device__ float g_cnt[NUM_SP];

__device__ __forceinline__ void grid_dep_wait() {
    asm volatile("griddepcontrol.wait;" ::: "memory");
}
__device__ __forceinline__ void grid_dep_trigger() {
    asm volatile("griddepcontrol.launch_dependents;" ::: "memory");
}

// -------------------------------------------------------------------------
// Kernel 1: zero scratch (vectorized)
// -------------------------------------------------------------------------
__global__ void zero_kernel() {
    int i = blockIdx.x * blockDim.x + threadIdx.x;
    reinterpret_cast<float4*>(g_sums)[i] = make_float4(0.f, 0.f, 0.f, 0.f);
    if (i < NUM_SP / 4)
        reinterpret_cast<float4*>(g_cnt)[i] = make_float4(0.f, 0.f, 0.f, 0.f);
}

// -------------------------------------------------------------------------
// Vectorized fire-and-forget global reduction (no "memory" clobber).
// -------------------------------------------------------------------------
__device__ __forceinline__ void red_add_v4(float* addr, float a, float b,
                                           float c, float d) {
    asm volatile("red.global.add.v4.f32 [%0], {%1, %2, %3, %4};"
                 :: "l"(addr), "f"(a), "f"(b), "f"(c), "f"(d));
}

// -------------------------------------------------------------------------
// Kernel 2: accumulate HALF the channels [cbase, cbase+32).
// Tile = 128 px x 32 ch. Same protected structure as the R8 floor kernel:
//   phase 1: coalesced streaming LDG.128, scalar-STS into swizzled
//            s_t[px][c4] (slot = px*8 + (c4 ^ ((px>>2)&7)), 2-way max)
//   phase 2: lanes 0-7 = 8 channel groups of ONE pixel -> each RED.v4
//            warp-instr covers 4 x 128B segment half-rows (4 lines).
// Counts are accumulated only by the cbase==0 half.
// grid_dep_wait(): for A0 orders after zero; for A1 it passes instantly
// (its predecessor G0 has already triggered by the time A1 launches).
// -------------------------------------------------------------------------
__global__ void __launch_bounds__(256) accum_kernel(
    const float* __restrict__ x, const int* __restrict__ sp, int cbase) {
    __shared__ float4 s_t[A_PX * 8];      // 16 KB, swizzled [px][c4]
    __shared__ int    s_seg[A_PX];

    int t  = threadIdx.x;
    int p0 = blockIdx.x * A_PX;

    if (t < A_PX / 4) {
        int4 v = reinterpret_cast<const int4*>(sp + p0)[t];
        s_seg[t * 4 + 0] = v.x;
        s_seg[t * 4 + 1] = v.y;
        s_seg[t * 4 + 2] = v.z;
        s_seg[t * 4 + 3] = v.w;
    }

    float* s_f = reinterpret_cast<float*>(s_t);
#pragma unroll
    for (int i = 0; i < 4; i++) {
        int idx = i * 256 + t;            // 0..1023
        int c   = idx >> 5;               // local channel 0..31
        int f   = idx & 31;               // float4 column 0..31
        float4 v = __ldcs(reinterpret_cast<const float4*>(
            x + (size_t)(cbase + c) * NPIX + p0 + f * 4));
        int c4 = c >> 2, comp = c & 3;
#pragma unroll
        for (int k = 0; k < 4; k++) {
            int px   = f * 4 + k;
            int slot = px * 8 + (c4 ^ (f & 7));   // f == px>>2
            s_f[slot * 4 + comp] = (&v.x)[k];
        }
    }
    __syncthreads();

    grid_dep_wait();   // A0: zero visible; A1: already triggered, no-op

    if (cbase == 0 && t < A_PX) atomicAdd(&g_cnt[s_seg[t]], 1.0f);

#pragma unroll
    for (int r = 0; r < 4; r++) {
        int pair = r * 256 + t;           // 0..1023
        int px   = pair >> 3;             // lanes 0-7 same px
        int cg   = pair & 7;
        int seg  = s_seg[px];
        float4 v = s_t[px * 8 + (cg ^ ((px >> 2) & 7))];
        red_add_v4(&g_sums[(size_t)seg * CCH + cbase + cg * 4],
                   v.x, v.y, v.z, v.w);
    }
}

// -------------------------------------------------------------------------
// Gather building blocks (protected R3 body, streaming stores)
// -------------------------------------------------------------------------
__device__ __forceinline__ void stage_means(float4* s_means, int cg, int tid) {
#pragma unroll
    for (int i = 0; i < NUM_SP / 256; i++) {
        int s = i * 256 + tid;
        float4 sum = *reinterpret_cast<const float4*>(
            &g_sums[(size_t)s * CCH + cg * 4]);
        float inv = __frcp_rn(fmaxf(g_cnt[s], 1.0f));
        s_means[s] = make_float4(sum.x * inv, sum.y * inv,
                                 sum.z * inv, sum.w * inv);
    }
}

__device__ __forceinline__ void gather_chunk(
    const int* __restrict__ sp, float* __restrict__ out,
    const float4* s_means, int cg, int pixBase, int tid) {
#pragma unroll
    for (int q = 0; q < QITER; q++) {
        int p = pixBase + (q * 256 + tid) * 4;
        int4 s4 = *reinterpret_cast<const int4*>(sp + p);

        float4 a = s_means[s4.x];
        float4 b = s_means[s4.y];
        float4 c = s_means[s4.z];
        float4 d = s_means[s4.w];

        __stcs(reinterpret_cast<float4*>(out + (size_t)(cg * 4 + 0) * NPIX + p),
               make_float4(a.x, b.x, c.x, d.x));
        __stcs(reinterpret_cast<float4*>(out + (size_t)(cg * 4 + 1) * NPIX + p),
               make_float4(a.y, b.y, c.y, d.y));
        __stcs(reinterpret_cast<float4*>(out + (size_t)(cg * 4 + 2) * NPIX + p),
               make_float4(a.z, b.z, c.z, d.z));
        __stcs(reinterpret_cast<float4*>(out + (size_t)(cg * 4 + 3) * NPIX + p),
               make_float4(a.w, b.w, c.w, d.w));
    }
}

// -------------------------------------------------------------------------
// Kernel 3a: G0 — persistent gather of channels 0-31 (cg 0..7).
// One co-resident wave (296 blocks, ~2/SM). After waiting for A0 it fires
// launch_dependents so A1 (PDL) starts immediately and overlaps G0.
// Block b: cg = b&7 fixed; chunks b>>3, +37, ... (<=2 tiles per block).
// -------------------------------------------------------------------------
__global__ void __launch_bounds__(256) gather0_kernel(
    const int* __restrict__ sp, float* __restrict__ out) {
    __shared__ float4 s_means[NUM_SP];    // 32 KB

    int tid = threadIdx.x;
    int cg  = blockIdx.x & 7;
    int chunk = blockIdx.x >> 3;

    grid_dep_wait();      // A0 complete (sums ch0-31 + counts final)
    grid_dep_trigger();   // release A1 now — it overlaps this kernel

    stage_means(s_means, cg, tid);
    __syncthreads();

    for (; chunk < N_CHUNKS; chunk += G0_STRIDE)
        gather_chunk(sp, out, s_means, cg, chunk * PIX_PER_TILE, tid);
}

// -------------------------------------------------------------------------
// Kernel 3b: G1 — gather of channels 32-63 (cg 8..15), normal grid.
// Runs after A1 completes (stream order / PDL trigger-at-completion).
// -------------------------------------------------------------------------
__global__ void __launch_bounds__(256) gather1_kernel(
    const int* __restrict__ sp, float* __restrict__ out) {
    __shared__ float4 s_means[NUM_SP];    // 32 KB

    int tid = threadIdx.x;
    int cg  = 8 + blockIdx.y;

    grid_dep_wait();      // A1's REDs visible

    stage_means(s_means, cg, tid);
    __syncthreads();

    gather_chunk(sp, out, s_means, cg, blockIdx.x * PIX_PER_TILE, tid);
}

// -------------------------------------------------------------------------
// kernel_launch: graph-capturable, single stream + PDL.
// Order: zero, A0[PDL], G0[PDL], A1[PDL], G1[PDL].
//   A0 overlaps zero's tail; G0 waits for A0 then immediately triggers A1;
//   A1 (atomic-ALU bound) runs concurrently with G0 (DRAM-write bound);
//   G1 runs after A1 completes.
// ncu capture slot #4 = A1 (the contended accum half).
// -------------------------------------------------------------------------
extern "C" void kernel_launch(void* const* d_in, const int* in_sizes, int n_in,
                              void* d_out, int out_size) {
    const float* x  = (const float*)d_in[0];
    const int*   sp = (const int*)d_in[1];
    float*       out = (float*)d_out;

    const int threads = 256;
    const int zero_blocks  = (NUM_SP * CCH / 4) / threads;   // 128
    const int accum_blocks = NPIX / A_PX;                    // 8192

    zero_kernel<<<zero_blocks, threads>>>();

    cudaLaunchAttribute pdl[1];
    pdl[0].id = cudaLaunchAttributeProgrammaticStreamSerialization;
    pdl[0].val.programmaticStreamSerializationAllowed = 1;

    {   // A0: channels 0-31 (+counts), overlaps zero
        cudaLaunchConfig_t cfg = {};
        cfg.gridDim  = dim3(accum_blocks);
        cfg.blockDim = dim3(threads);
        cfg.stream   = 0;
        cfg.attrs    = pdl;
        cfg.numAttrs = 1;
        int cbase = 0;
        cudaLaunchKernelEx(&cfg, accum_kernel, x, sp, cbase);
    }
    {   // G0: persistent gather ch 0-31; triggers A1 early
        cudaLaunchConfig_t cfg = {};
        cfg.gridDim  = dim3(G0_BLOCKS);
        cfg.blockDim = dim3(threads);
        cfg.stream   = 0;
        cfg.attrs    = pdl;
        cfg.numAttrs = 1;
        cudaLaunchKernelEx(&cfg, gather0_kernel, sp, out);
    }
    {   // A1: channels 32-63, launches at G0's trigger -> overlaps G0
        cudaLaunchConfig_t cfg = {};
        cfg.gridDim  = dim3(accum_blocks);
        cfg.blockDim = dim3(threads);
        cfg.stream   = 0;
        cfg.attrs    = pdl;
        cfg.numAttrs = 1;
        int cbase = 32;
        cudaLaunchKernelEx(&cfg, accum_kernel, x, sp, cbase);
    }
    {   // G1: gather ch 32-63 after A1 completes
        cudaLaunchConfig_t cfg = {};
        cfg.gridDim  = dim3(N_CHUNKS, 8);
        cfg.blockDim = dim3(threads);
        cfg.stream   = 0;
        cfg.attrs    = pdl;
        cfg.numAttrs = 1;
        cudaLaunchKernelEx(&cfg, gather1_kernel, sp, out);
    }
}